// round 10
// baseline (speedup 1.0000x reference)
#include <cuda_runtime.h>
#include <cuda_fp16.h>

#define NN   100000
#define NE   1600000
#define INC  128
#define OUTC 64
#define NBLK 391                      // ceil(NN/256)

// ---- scratch (__device__ globals; zero-initialized at load) ----------------
__device__ unsigned           g_h16[NN * OUTC / 2];  // h as half2, 12.8 MB
__device__ unsigned long long g_pack[NN];            // {cnt:20 @bit44 | deg fixpt 2^-32}
__device__ float              g_dis[NN];
__device__ int                g_bsum[NBLK];
__device__ int                g_bpre[NBLK];
__device__ int                g_off[NN + 1];
__device__ int                g_cur[NN];
__device__ unsigned long long g_rec[NE];             // packed {row:int32, norm:f32}

// ---------------------------------------------------------------------------
// per-thread dtype detect: int64 indices < 100000 -> zero high words
// ---------------------------------------------------------------------------
__device__ __forceinline__ bool detect64(const int* ei32) {
    return ei32[1] == 0 && ei32[3] == 0 && ei32[5] == 0;   // L1-broadcast hits
}
__device__ __forceinline__ int load_idx(const void* ei, bool is64, long long pos) {
    if (is64) return (int)((const long long*)ei)[pos];
    return ((const int*)ei)[pos];
}

// ---------------------------------------------------------------------------
// count: single fused 64-bit atomic per edge. cnt at bit 44, deg fixed-point
// (scale 2^-32) in low 44 bits.  deg <= ~64 -> max 2^38, no overflow into cnt.
// ---------------------------------------------------------------------------
__global__ void k_count(const int* __restrict__ ei32, const float* __restrict__ ew) {
    int e = blockIdx.x * 256 + threadIdx.x;
    if (e >= NE) return;
    bool is64 = detect64(ei32);
    int col = load_idx(ei32, is64, (long long)NE + e);
    unsigned long long fx = (unsigned long long)((double)ew[e] * 4294967296.0);
    atomicAdd(&g_pack[col], (1ULL << 44) | fx);
}

// per-block sums of cnt
__global__ void k_scan1() {
    __shared__ int s[256];
    int t = threadIdx.x;
    int i = blockIdx.x * 256 + t;
    s[t] = (i < NN) ? (int)(g_pack[i] >> 44) : 0;
    __syncthreads();
    #pragma unroll
    for (int st = 128; st > 0; st >>= 1) {
        if (t < st) s[t] += s[t + st];
        __syncthreads();
    }
    if (t == 0) g_bsum[blockIdx.x] = s[0];
}

// exclusive scan of block sums (single block)
__global__ void k_scan2() {
    __shared__ int s[512];
    int t = threadIdx.x;
    s[t] = (t < NBLK) ? g_bsum[t] : 0;
    __syncthreads();
    #pragma unroll
    for (int st = 1; st < 512; st <<= 1) {
        int v = (t >= st) ? s[t - st] : 0;
        __syncthreads();
        s[t] += v;
        __syncthreads();
    }
    if (t < NBLK) g_bpre[t] = (t == 0) ? 0 : s[t - 1];
    if (t == 0)   g_off[NN] = NE;
}

// offsets + cursors + dis = rsqrt(deg); self-clean g_pack for next replay
__global__ void k_scan3() {
    __shared__ int s[256];
    int t = threadIdx.x;
    int i = blockIdx.x * 256 + t;
    unsigned long long pack = (i < NN) ? g_pack[i] : 0ULL;
    int v = (int)(pack >> 44);
    s[t] = v;
    __syncthreads();
    #pragma unroll
    for (int st = 1; st < 256; st <<= 1) {
        int u = (t >= st) ? s[t - st] : 0;
        __syncthreads();
        s[t] += u;
        __syncthreads();
    }
    if (i < NN) {
        int off = g_bpre[blockIdx.x] + s[t] - v;   // exclusive
        g_off[i] = off;
        g_cur[i] = off;
        double deg = (double)(pack & ((1ULL << 44) - 1)) * (1.0 / 4294967296.0);
        g_dis[i] = (deg > 0.0) ? rsqrtf((float)deg) : 0.f;
        g_pack[i] = 0ULL;                          // self-clean for next call
    }
}

// fill CSR: rec[pos] = {row, norm}
__global__ void k_fill(const int* __restrict__ ei32, const float* __restrict__ ew) {
    int e = blockIdx.x * 256 + threadIdx.x;
    if (e >= NE) return;
    bool is64 = detect64(ei32);
    int row = load_idx(ei32, is64, e);
    int col = load_idx(ei32, is64, (long long)NE + e);
    float norm = g_dis[row] * ew[e] * g_dis[col];
    int pos = atomicAdd(&g_cur[col], 1);
    unsigned long long r = (unsigned int)row |
                           ((unsigned long long)__float_as_uint(norm) << 32);
    g_rec[pos] = r;
}

// ---------------------------------------------------------------------------
// GEMM: h = X @ W in fp32 (f32x2 FFMA), stored as half2.
// 2 rows/thread, 16 cols/thread. W in shared (32 KB, broadcast LDS).
// ---------------------------------------------------------------------------
__device__ __forceinline__ unsigned long long ffma2(unsigned long long a,
                                                    unsigned long long b,
                                                    unsigned long long c) {
    unsigned long long d;
    asm("fma.rn.f32x2 %0, %1, %2, %3;" : "=l"(d) : "l"(a), "l"(b), "l"(c));
    return d;
}
__device__ __forceinline__ unsigned long long pack2(float lo) {
    unsigned long long d;
    asm("mov.b64 %0, {%1, %1};" : "=l"(d) : "f"(lo));
    return d;
}
__device__ __forceinline__ unsigned tohalf2(unsigned long long v) {
    float lo, hi;
    asm("mov.b64 {%0, %1}, %2;" : "=f"(lo), "=f"(hi) : "l"(v));
    unsigned r;
    asm("cvt.rn.f16x2.f32 %0, %1, %2;" : "=r"(r) : "f"(hi), "f"(lo));
    return r;
}

__global__ void __launch_bounds__(256) k_gemm(const float* __restrict__ x,
                                              const float* __restrict__ W) {
    __shared__ unsigned long long Wsu[INC * OUTC / 2];   // 32 KB
    int t = threadIdx.x;
    const unsigned long long* Wg = (const unsigned long long*)W;
    #pragma unroll
    for (int i = 0; i < 16; i++) Wsu[t + 256 * i] = Wg[t + 256 * i];
    __syncthreads();

    int cg = t & 3;
    int r0 = blockIdx.x * 128 + (t >> 2) * 2;
    if (r0 >= NN) return;
    bool has1 = (r0 + 1) < NN;

    unsigned long long a0[8] = {0,0,0,0,0,0,0,0};
    unsigned long long a1[8] = {0,0,0,0,0,0,0,0};

    const float4* xr0 = (const float4*)(x + (long long)r0 * INC);
    const float4* xr1 = (const float4*)(x + (long long)(has1 ? r0 + 1 : r0) * INC);

    #pragma unroll 2
    for (int k4 = 0; k4 < 32; k4++) {
        float4 xv0 = __ldg(&xr0[k4]);
        float4 xv1 = __ldg(&xr1[k4]);
        float xs0[4] = {xv0.x, xv0.y, xv0.z, xv0.w};
        float xs1[4] = {xv1.x, xv1.y, xv1.z, xv1.w};
        #pragma unroll
        for (int kk = 0; kk < 4; kk++) {
            int k = k4 * 4 + kk;
            unsigned long long xx0 = pack2(xs0[kk]);
            unsigned long long xx1 = pack2(xs1[kk]);
            const unsigned long long* wrow = &Wsu[k * 32 + cg * 8];
            #pragma unroll
            for (int j = 0; j < 8; j++) {
                unsigned long long w = wrow[j];
                a0[j] = ffma2(xx0, w, a0[j]);
                a1[j] = ffma2(xx1, w, a1[j]);
            }
        }
    }

    unsigned h0[8], h1[8];
    #pragma unroll
    for (int j = 0; j < 8; j++) {
        h0[j] = tohalf2(a0[j]);
        h1[j] = tohalf2(a1[j]);
    }
    uint4* hv = (uint4*)g_h16;                     // 8 uint4 per row
    long long base0 = (long long)r0 * 8 + cg * 2;
    hv[base0 + 0] = make_uint4(h0[0], h0[1], h0[2], h0[3]);
    hv[base0 + 1] = make_uint4(h0[4], h0[5], h0[6], h0[7]);
    if (has1) {
        hv[base0 + 8] = make_uint4(h1[0], h1[1], h1[2], h1[3]);
        hv[base0 + 9] = make_uint4(h1[4], h1[5], h1[6], h1[7]);
    }
}

// ---------------------------------------------------------------------------
// gather: 8 threads/node, each lane owns one uint4 (8 halves) of the h row.
// unroll 8 for deep MLP against L2 latency. fp32 accumulate, sigmoid fused.
// ---------------------------------------------------------------------------
__device__ __forceinline__ void acc_line(float2* a, uint4 v, float norm) {
    float2 f0 = __half22float2(*(__half2*)&v.x);
    float2 f1 = __half22float2(*(__half2*)&v.y);
    float2 f2 = __half22float2(*(__half2*)&v.z);
    float2 f3 = __half22float2(*(__half2*)&v.w);
    a[0].x += norm * f0.x; a[0].y += norm * f0.y;
    a[1].x += norm * f1.x; a[1].y += norm * f1.y;
    a[2].x += norm * f2.x; a[2].y += norm * f2.y;
    a[3].x += norm * f3.x; a[3].y += norm * f3.y;
}

__global__ void __launch_bounds__(256) k_gather(const float4* __restrict__ b4,
                                                float4* __restrict__ out) {
    int gid = blockIdx.x * 256 + threadIdx.x;    // exactly NN*8 threads
    int n = gid >> 3;
    if (n >= NN) return;
    int j = gid & 7;                             // owns cols j*8 .. j*8+7

    int p   = g_off[n];
    int end = g_off[n + 1];

    float4 blo = __ldg(&b4[j * 2]);
    float4 bhi = __ldg(&b4[j * 2 + 1]);
    float2 acc[4] = {{blo.x, blo.y}, {blo.z, blo.w}, {bhi.x, bhi.y}, {bhi.z, bhi.w}};

    const uint4* h4 = (const uint4*)g_h16;

    // unrolled by 8: 8 independent line loads in flight
    for (; p + 8 <= end; p += 8) {
        unsigned long long r[8];
        #pragma unroll
        for (int q = 0; q < 8; q++) r[q] = g_rec[p + q];
        uint4 v[8];
        #pragma unroll
        for (int q = 0; q < 8; q++)
            v[q] = __ldg(&h4[(int)(unsigned)(r[q] & 0xffffffffu) * 8 + j]);
        #pragma unroll
        for (int q = 0; q < 8; q++)
            acc_line(acc, v[q], __uint_as_float((unsigned)(r[q] >> 32)));
    }
    for (; p + 2 <= end; p += 2) {
        unsigned long long r0 = g_rec[p], r1 = g_rec[p + 1];
        uint4 v0 = __ldg(&h4[(int)(unsigned)(r0 & 0xffffffffu) * 8 + j]);
        uint4 v1 = __ldg(&h4[(int)(unsigned)(r1 & 0xffffffffu) * 8 + j]);
        acc_line(acc, v0, __uint_as_float((unsigned)(r0 >> 32)));
        acc_line(acc, v1, __uint_as_float((unsigned)(r1 >> 32)));
    }
    if (p < end) {
        unsigned long long r = g_rec[p];
        uint4 v = __ldg(&h4[(int)(unsigned)(r & 0xffffffffu) * 8 + j]);
        acc_line(acc, v, __uint_as_float((unsigned)(r >> 32)));
    }

    float4 o0, o1;
    o0.x = 1.f / (1.f + __expf(-acc[0].x));
    o0.y = 1.f / (1.f + __expf(-acc[0].y));
    o0.z = 1.f / (1.f + __expf(-acc[1].x));
    o0.w = 1.f / (1.f + __expf(-acc[1].y));
    o1.x = 1.f / (1.f + __expf(-acc[2].x));
    o1.y = 1.f / (1.f + __expf(-acc[2].y));
    o1.z = 1.f / (1.f + __expf(-acc[3].x));
    o1.w = 1.f / (1.f + __expf(-acc[3].y));
    out[n * 16 + j * 2]     = o0;
    out[n * 16 + j * 2 + 1] = o1;
}

// ---------------------------------------------------------------------------
extern "C" void kernel_launch(void* const* d_in, const int* in_sizes, int n_in,
                              void* d_out, int out_size) {
    const float* x  = (const float*)d_in[0];
    const int*   ei = (const int*)d_in[1];
    const float* ew = (const float*)d_in[2];
    const float* W  = (const float*)d_in[3];
    const float* b  = (const float*)d_in[4];
    float* out = (float*)d_out;

    k_count <<<(NE + 255) / 256, 256>>>(ei, ew);
    k_scan1 <<<NBLK, 256>>>();
    k_scan2 <<<1, 512>>>();
    k_scan3 <<<NBLK, 256>>>();
    k_fill  <<<(NE + 255) / 256, 256>>>(ei, ew);
    k_gemm  <<<(NN + 127) / 128, 256>>>(x, W);   // h written right before gather (L2-hot)
    k_gather<<<NN * 8 / 256, 256>>>((const float4*)b, (float4*)out);
}

// round 12
// speedup vs baseline: 1.5647x; 1.5647x over previous
#include <cuda_runtime.h>
#include <cuda_fp16.h>

#define NN   100000
#define NE   1600000
#define INC  128
#define OUTC 64
#define NBLK 391                      // ceil(NN/256)

// ---- scratch (__device__ globals; zero-initialized at load) ----------------
__device__ unsigned           g_h16[NN * OUTC / 2];  // h as half2, 12.8 MB
__device__ unsigned long long g_pack[NN];            // {cnt @bit44 | deg fixpt 2^-32}
__device__ float              g_dis[NN];
__device__ int                g_bsum[NBLK];
__device__ int                g_bpre[NBLK];
__device__ int                g_off[NN + 1];
__device__ int                g_cur[NN];
__device__ unsigned long long g_rec[NE];             // packed {row:int32, norm:f32}

// ---------------------------------------------------------------------------
// per-thread dtype detect: int64 indices < 100000 -> zero high words
// ---------------------------------------------------------------------------
__device__ __forceinline__ bool detect64(const int* ei32) {
    return ei32[1] == 0 && ei32[3] == 0 && ei32[5] == 0;   // L1-broadcast hits
}
__device__ __forceinline__ int load_idx(const void* ei, bool is64, long long pos) {
    if (is64) return (int)((const long long*)ei)[pos];
    return ((const int*)ei)[pos];
}

// ---------------------------------------------------------------------------
// count: ONE fused 64-bit atomic per edge. cnt at bit 44, deg fixed-point
// (scale 2^-32) in low 44 bits.  ALL FP32 — no fp64 anywhere (R10 lesson).
// fp32 conv err <= 2^-24 absolute per edge -> deg rel err ~1e-8.
// ---------------------------------------------------------------------------
__global__ void k_count(const int* __restrict__ ei32, const float* __restrict__ ew) {
    int e = blockIdx.x * 256 + threadIdx.x;
    if (e >= NE) return;
    bool is64 = detect64(ei32);
    int col = load_idx(ei32, is64, (long long)NE + e);
    unsigned long long fx = (unsigned long long)(ew[e] * 4294967296.0f);
    atomicAdd(&g_pack[col], (1ULL << 44) | fx);
}

// per-block sums of cnt
__global__ void k_scan1() {
    __shared__ int s[256];
    int t = threadIdx.x;
    int i = blockIdx.x * 256 + t;
    s[t] = (i < NN) ? (int)(g_pack[i] >> 44) : 0;
    __syncthreads();
    #pragma unroll
    for (int st = 128; st > 0; st >>= 1) {
        if (t < st) s[t] += s[t + st];
        __syncthreads();
    }
    if (t == 0) g_bsum[blockIdx.x] = s[0];
}

// exclusive scan of block sums (single block)
__global__ void k_scan2() {
    __shared__ int s[512];
    int t = threadIdx.x;
    s[t] = (t < NBLK) ? g_bsum[t] : 0;
    __syncthreads();
    #pragma unroll
    for (int st = 1; st < 512; st <<= 1) {
        int v = (t >= st) ? s[t - st] : 0;
        __syncthreads();
        s[t] += v;
        __syncthreads();
    }
    if (t < NBLK) g_bpre[t] = (t == 0) ? 0 : s[t - 1];
    if (t == 0)   g_off[NN] = NE;
}

// offsets + cursors + dis = rsqrt(deg); self-clean g_pack for next replay
__global__ void k_scan3() {
    __shared__ int s[256];
    int t = threadIdx.x;
    int i = blockIdx.x * 256 + t;
    unsigned long long pack = (i < NN) ? g_pack[i] : 0ULL;
    int v = (int)(pack >> 44);
    s[t] = v;
    __syncthreads();
    #pragma unroll
    for (int st = 1; st < 256; st <<= 1) {
        int u = (t >= st) ? s[t - st] : 0;
        __syncthreads();
        s[t] += u;
        __syncthreads();
    }
    if (i < NN) {
        int off = g_bpre[blockIdx.x] + s[t] - v;   // exclusive
        g_off[i] = off;
        g_cur[i] = off;
        float deg = (float)(pack & ((1ULL << 44) - 1)) * 2.3283064365386963e-10f;
        g_dis[i] = (deg > 0.f) ? rsqrtf(deg) : 0.f;
        g_pack[i] = 0ULL;                          // self-clean for next call
    }
}

// fill CSR: rec[pos] = {row, norm}
__global__ void k_fill(const int* __restrict__ ei32, const float* __restrict__ ew) {
    int e = blockIdx.x * 256 + threadIdx.x;
    if (e >= NE) return;
    bool is64 = detect64(ei32);
    int row = load_idx(ei32, is64, e);
    int col = load_idx(ei32, is64, (long long)NE + e);
    float norm = g_dis[row] * ew[e] * g_dis[col];
    int pos = atomicAdd(&g_cur[col], 1);
    unsigned long long r = (unsigned int)row |
                           ((unsigned long long)__float_as_uint(norm) << 32);
    g_rec[pos] = r;
}

// ---------------------------------------------------------------------------
// GEMM: h = X @ W in fp32 (f32x2 FFMA), stored as half2.
// 2 rows/thread, 16 cols/thread. W in shared (32 KB, broadcast LDS).
// ---------------------------------------------------------------------------
__device__ __forceinline__ unsigned long long ffma2(unsigned long long a,
                                                    unsigned long long b,
                                                    unsigned long long c) {
    unsigned long long d;
    asm("fma.rn.f32x2 %0, %1, %2, %3;" : "=l"(d) : "l"(a), "l"(b), "l"(c));
    return d;
}
__device__ __forceinline__ unsigned long long pack2(float lo) {
    unsigned long long d;
    asm("mov.b64 %0, {%1, %1};" : "=l"(d) : "f"(lo));
    return d;
}
__device__ __forceinline__ unsigned tohalf2(unsigned long long v) {
    float lo, hi;
    asm("mov.b64 {%0, %1}, %2;" : "=f"(lo), "=f"(hi) : "l"(v));
    unsigned r;
    asm("cvt.rn.f16x2.f32 %0, %1, %2;" : "=r"(r) : "f"(hi), "f"(lo));
    return r;
}

__global__ void __launch_bounds__(256) k_gemm(const float* __restrict__ x,
                                              const float* __restrict__ W) {
    __shared__ unsigned long long Wsu[INC * OUTC / 2];   // 32 KB
    int t = threadIdx.x;
    const unsigned long long* Wg = (const unsigned long long*)W;
    #pragma unroll
    for (int i = 0; i < 16; i++) Wsu[t + 256 * i] = Wg[t + 256 * i];
    __syncthreads();

    int cg = t & 3;
    int r0 = blockIdx.x * 128 + (t >> 2) * 2;
    if (r0 >= NN) return;
    bool has1 = (r0 + 1) < NN;

    unsigned long long a0[8] = {0,0,0,0,0,0,0,0};
    unsigned long long a1[8] = {0,0,0,0,0,0,0,0};

    const float4* xr0 = (const float4*)(x + (long long)r0 * INC);
    const float4* xr1 = (const float4*)(x + (long long)(has1 ? r0 + 1 : r0) * INC);

    #pragma unroll 2
    for (int k4 = 0; k4 < 32; k4++) {
        float4 xv0 = __ldg(&xr0[k4]);
        float4 xv1 = __ldg(&xr1[k4]);
        float xs0[4] = {xv0.x, xv0.y, xv0.z, xv0.w};
        float xs1[4] = {xv1.x, xv1.y, xv1.z, xv1.w};
        #pragma unroll
        for (int kk = 0; kk < 4; kk++) {
            int k = k4 * 4 + kk;
            unsigned long long xx0 = pack2(xs0[kk]);
            unsigned long long xx1 = pack2(xs1[kk]);
            const unsigned long long* wrow = &Wsu[k * 32 + cg * 8];
            #pragma unroll
            for (int j = 0; j < 8; j++) {
                unsigned long long w = wrow[j];
                a0[j] = ffma2(xx0, w, a0[j]);
                a1[j] = ffma2(xx1, w, a1[j]);
            }
        }
    }

    unsigned h0[8], h1[8];
    #pragma unroll
    for (int j = 0; j < 8; j++) {
        h0[j] = tohalf2(a0[j]);
        h1[j] = tohalf2(a1[j]);
    }
    uint4* hv = (uint4*)g_h16;                     // 8 uint4 per row
    long long base0 = (long long)r0 * 8 + cg * 2;
    hv[base0 + 0] = make_uint4(h0[0], h0[1], h0[2], h0[3]);
    hv[base0 + 1] = make_uint4(h0[4], h0[5], h0[6], h0[7]);
    if (has1) {
        hv[base0 + 8] = make_uint4(h1[0], h1[1], h1[2], h1[3]);
        hv[base0 + 9] = make_uint4(h1[4], h1[5], h1[6], h1[7]);
    }
}

// ---------------------------------------------------------------------------
// gather: 8 threads/node, each lane owns one uint4 (8 halves) of the h row.
// unroll 8 for deep MLP against L2 latency. fp32 accumulate, sigmoid fused.
// ---------------------------------------------------------------------------
__device__ __forceinline__ void acc_line(float2* a, uint4 v, float norm) {
    float2 f0 = __half22float2(*(__half2*)&v.x);
    float2 f1 = __half22float2(*(__half2*)&v.y);
    float2 f2 = __half22float2(*(__half2*)&v.z);
    float2 f3 = __half22float2(*(__half2*)&v.w);
    a[0].x += norm * f0.x; a[0].y += norm * f0.y;
    a[1].x += norm * f1.x; a[1].y += norm * f1.y;
    a[2].x += norm * f2.x; a[2].y += norm * f2.y;
    a[3].x += norm * f3.x; a[3].y += norm * f3.y;
}

__global__ void __launch_bounds__(256) k_gather(const float4* __restrict__ b4,
                                                float4* __restrict__ out) {
    int gid = blockIdx.x * 256 + threadIdx.x;    // exactly NN*8 threads
    int n = gid >> 3;
    if (n >= NN) return;
    int j = gid & 7;                             // owns cols j*8 .. j*8+7

    int p   = g_off[n];
    int end = g_off[n + 1];

    float4 blo = __ldg(&b4[j * 2]);
    float4 bhi = __ldg(&b4[j * 2 + 1]);
    float2 acc[4] = {{blo.x, blo.y}, {blo.z, blo.w}, {bhi.x, bhi.y}, {bhi.z, bhi.w}};

    const uint4* h4 = (const uint4*)g_h16;

    // unrolled by 8: 8 independent line loads in flight
    for (; p + 8 <= end; p += 8) {
        unsigned long long r[8];
        #pragma unroll
        for (int q = 0; q < 8; q++) r[q] = g_rec[p + q];
        uint4 v[8];
        #pragma unroll
        for (int q = 0; q < 8; q++)
            v[q] = __ldg(&h4[(int)(unsigned)(r[q] & 0xffffffffu) * 8 + j]);
        #pragma unroll
        for (int q = 0; q < 8; q++)
            acc_line(acc, v[q], __uint_as_float((unsigned)(r[q] >> 32)));
    }
    for (; p + 2 <= end; p += 2) {
        unsigned long long r0 = g_rec[p], r1 = g_rec[p + 1];
        uint4 v0 = __ldg(&h4[(int)(unsigned)(r0 & 0xffffffffu) * 8 + j]);
        uint4 v1 = __ldg(&h4[(int)(unsigned)(r1 & 0xffffffffu) * 8 + j]);
        acc_line(acc, v0, __uint_as_float((unsigned)(r0 >> 32)));
        acc_line(acc, v1, __uint_as_float((unsigned)(r1 >> 32)));
    }
    if (p < end) {
        unsigned long long r = g_rec[p];
        uint4 v = __ldg(&h4[(int)(unsigned)(r & 0xffffffffu) * 8 + j]);
        acc_line(acc, v, __uint_as_float((unsigned)(r >> 32)));
    }

    float4 o0, o1;
    o0.x = 1.f / (1.f + __expf(-acc[0].x));
    o0.y = 1.f / (1.f + __expf(-acc[0].y));
    o0.z = 1.f / (1.f + __expf(-acc[1].x));
    o0.w = 1.f / (1.f + __expf(-acc[1].y));
    o1.x = 1.f / (1.f + __expf(-acc[2].x));
    o1.y = 1.f / (1.f + __expf(-acc[2].y));
    o1.z = 1.f / (1.f + __expf(-acc[3].x));
    o1.w = 1.f / (1.f + __expf(-acc[3].y));
    out[n * 16 + j * 2]     = o0;
    out[n * 16 + j * 2 + 1] = o1;
}

// ---------------------------------------------------------------------------
extern "C" void kernel_launch(void* const* d_in, const int* in_sizes, int n_in,
                              void* d_out, int out_size) {
    const float* x  = (const float*)d_in[0];
    const int*   ei = (const int*)d_in[1];
    const float* ew = (const float*)d_in[2];
    const float* W  = (const float*)d_in[3];
    const float* b  = (const float*)d_in[4];
    float* out = (float*)d_out;

    k_count <<<(NE + 255) / 256, 256>>>(ei, ew);
    k_scan1 <<<NBLK, 256>>>();
    k_scan2 <<<1, 512>>>();
    k_scan3 <<<NBLK, 256>>>();
    k_fill  <<<(NE + 255) / 256, 256>>>(ei, ew);
    k_gemm  <<<(NN + 127) / 128, 256>>>(x, W);   // h written right before gather (L2-hot)
    k_gather<<<NN * 8 / 256, 256>>>((const float4*)b, (float4*)out);
}